// round 10
// baseline (speedup 1.0000x reference)
#include <cuda_runtime.h>
#include <cuda_bf16.h>

#define N_NODES 50000
#define N_EDGES 400000
#define N_GRAPHS 64
#define EDGE_GRID 296

typedef unsigned long long u64;

// Packed fp32x2 helpers (Blackwell FFMA2 path)
__device__ __forceinline__ u64 pack2(float a, float b) {
    u64 r; asm("mov.b64 %0,{%1,%2};" : "=l"(r) : "f"(a), "f"(b)); return r;
}
__device__ __forceinline__ u64 fma2(u64 a, u64 b, u64 c) {
    u64 d; asm("fma.rn.f32x2 %0,%1,%2,%3;" : "=l"(d) : "l"(a), "l"(b), "l"(c)); return d;
}
__device__ __forceinline__ float hadd2(u64 v) {
    float lo, hi; asm("mov.b64 {%0,%1},%2;" : "=f"(lo), "=f"(hi) : "l"(v)); return lo + hi;
}
__device__ __forceinline__ u64 relu2(u64 v) {
    float lo, hi; asm("mov.b64 {%0,%1},%2;" : "=f"(lo), "=f"(hi) : "l"(v));
    return pack2(fmaxf(lo, 0.f), fmaxf(hi, 0.f));
}

// Scratch (device globals; no allocation allowed)
__device__ float g_buf1[N_NODES * 32];   // conv1 accumulator (pre-relu)
__device__ float g_buf2[N_NODES * 16];   // conv2 accumulator
__device__ float g_pool[N_GRAPHS * 16];  // pooled graph features

// ---------------------------------------------------------------------------
// K1: agg1[n,o] = c1_bias[o] + sum_i x[n,i] * c1_root[i,o]
// ---------------------------------------------------------------------------
__global__ void node_init1(const float* __restrict__ x,
                           const float* __restrict__ root,
                           const float* __restrict__ bias) {
    int t = blockIdx.x * blockDim.x + threadIdx.x;
    if (t >= N_NODES * 32) return;
    int n = t >> 5, o = t & 31;
    const float* xr = x + n * 16;
    float acc = bias[o];
#pragma unroll
    for (int i = 0; i < 16; i++) acc = fmaf(xr[i], root[i * 32 + o], acc);
    g_buf1[t] = acc;
}

// ---------------------------------------------------------------------------
// K2: conv1 edge kernel. Persistent; warp = 4 edges; lane = out channel (32).
// 2 CTAs/SM (regs capped at 128 via launch_bounds) -> 4 warps/SMSP.
// ---------------------------------------------------------------------------
__global__ __launch_bounds__(256, 2) void edge1(
    const float* __restrict__ x, const int* __restrict__ ei,
    const float* __restrict__ ea,
    const float* __restrict__ w1, const float* __restrict__ b1,
    const float* __restrict__ w2, const float* __restrict__ b2) {
    extern __shared__ u64 sm[];
    u64* s_w2p = sm;                       // 32*8*32 = 8192
    u64* s_b2p = sm + 8192;                // 256
    u64* s_hA  = sm + 8448;                // 8 warps * 132 = 1056
    u64* s_xA  = sm + 9504;                // 8 warps * 32  = 256
    float* s_w1 = (float*)(sm + 9760);     // 256 floats (128 u64)
    float* s_b1 = (float*)(sm + 9888);     // 32 floats (16 u64)
    // total 9904 u64 = 79232 B

    int tid = threadIdx.x;
    for (int idx = tid; idx < 8192; idx += 256) {
        int k = idx >> 8, r = idx & 255;
        int ip = r >> 5, o = r & 31;
        s_w2p[idx] = pack2(w2[k * 512 + ip * 64 + o], w2[k * 512 + ip * 64 + 32 + o]);
    }
    {
        int ip = tid >> 5, o = tid & 31;
        s_b2p[tid] = pack2(b2[ip * 64 + o], b2[ip * 64 + 32 + o]);
        s_w1[tid] = w1[tid];
    }
    if (tid < 32) s_b1[tid] = b1[tid];
    __syncthreads();

    int warp = tid >> 5, lane = tid & 31;
    u64* sh = s_hA + warp * 132;
    u64* sx = s_xA + warp * 32;

    const long NG = N_EDGES / 4;
    const long stride = (long)EDGE_GRID * 8;

    for (long g = (long)blockIdx.x * 8 + warp; g < NG; g += stride) {
        long e0 = g * 4;
        // dst indices into registers (static indexing only)
        int dsts[4];
#pragma unroll
        for (int e = 0; e < 4; e++) dsts[e] = __ldg(ei + N_EDGES + e0 + e);
        // cooperative x-gather: lane covers word lane (4 edges * 8 u64)
        {
            int e = lane >> 3, ip = lane & 7;
            int src = __ldg(ei + e0 + e);
            sx[lane] = __ldg((const u64*)x + (long)src * 8 + ip);
        }
        // edge-MLP (direct ea loads)
#pragma unroll
        for (int e = 0; e < 4; e++) {
            const float4* ear = (const float4*)(ea + (e0 + e) * 8);
            float4 a0 = __ldg(ear), a1 = __ldg(ear + 1);
            float acc = s_b1[lane];
            acc = fmaf(a0.x, s_w1[0 * 32 + lane], acc);
            acc = fmaf(a0.y, s_w1[1 * 32 + lane], acc);
            acc = fmaf(a0.z, s_w1[2 * 32 + lane], acc);
            acc = fmaf(a0.w, s_w1[3 * 32 + lane], acc);
            acc = fmaf(a1.x, s_w1[4 * 32 + lane], acc);
            acc = fmaf(a1.y, s_w1[5 * 32 + lane], acc);
            acc = fmaf(a1.z, s_w1[6 * 32 + lane], acc);
            acc = fmaf(a1.w, s_w1[7 * 32 + lane], acc);
            acc = fmaxf(acc, 0.f);
            sh[e * 33 + lane] = pack2(acc, acc);
        }
        __syncwarp();

        // mainloop: acc init from b2 pairs
        u64 acc[4][8];
#pragma unroll
        for (int ip = 0; ip < 8; ip++) {
            u64 b = s_b2p[ip * 32 + lane];
#pragma unroll
            for (int e = 0; e < 4; e++) acc[e][ip] = b;
        }
#pragma unroll 4
        for (int k = 0; k < 32; k++) {
            u64 h[4];
#pragma unroll
            for (int e = 0; e < 4; e++) h[e] = sh[e * 33 + k];
            const u64* wr = s_w2p + k * 256 + lane;
#pragma unroll
            for (int ip = 0; ip < 8; ip++) {
                u64 w = wr[ip * 32];
#pragma unroll
                for (int e = 0; e < 4; e++) acc[e][ip] = fma2(h[e], w, acc[e][ip]);
            }
        }
        __syncwarp();

        // epilogue: contract with staged x, scatter-add
#pragma unroll
        for (int e = 0; e < 4; e++) {
            u64 s = 0ull;
#pragma unroll
            for (int ip = 0; ip < 8; ip++) s = fma2(sx[e * 8 + ip], acc[e][ip], s);
            atomicAdd(&g_buf1[(long)dsts[e] * 32 + lane], hadd2(s));
        }
        __syncwarp();  // protect sx before next iteration's overwrite
    }
}

// ---------------------------------------------------------------------------
// K4: agg2[n,o] = c2_bias[o] + sum_i relu(agg1[n,i]) * c2_root[i,o]
// ---------------------------------------------------------------------------
__global__ void node_init2(const float* __restrict__ root,
                           const float* __restrict__ bias) {
    int t = blockIdx.x * blockDim.x + threadIdx.x;
    if (t >= N_NODES * 16) return;
    int n = t >> 4, o = t & 15;
    const float* xr = g_buf1 + n * 32;
    float acc = bias[o];
#pragma unroll
    for (int i = 0; i < 32; i++) acc = fmaf(fmaxf(xr[i], 0.f), root[i * 16 + o], acc);
    g_buf2[t] = acc;
}

// ---------------------------------------------------------------------------
// K5: conv2 edge kernel. Persistent; warp = 4 edges; half-warp sub owns 2.
// 2 CTAs/SM -> 4 warps/SMSP. relu fused into gather.
// ---------------------------------------------------------------------------
__global__ __launch_bounds__(256, 2) void edge2(
    const int* __restrict__ ei, const float* __restrict__ ea,
    const float* __restrict__ w1, const float* __restrict__ b1,
    const float* __restrict__ w2, const float* __restrict__ b2) {
    extern __shared__ u64 sm[];
    u64* s_w2p = sm;                       // 32*16*16 = 8192
    u64* s_b2p = sm + 8192;                // 256
    u64* s_hA  = sm + 8448;                // 1056
    u64* s_xA  = sm + 9504;                // 8 warps * 64 = 512
    float* s_w1 = (float*)(sm + 10016);    // 256 floats (128 u64)
    float* s_b1 = (float*)(sm + 10144);    // 32 floats (16 u64)
    // total 10160 u64 = 81280 B

    int tid = threadIdx.x;
    for (int idx = tid; idx < 8192; idx += 256) {
        int k = idx >> 8, r = idx & 255;
        int ip = r >> 4, o = r & 15;
        s_w2p[idx] = pack2(w2[k * 512 + ip * 32 + o], w2[k * 512 + ip * 32 + 16 + o]);
    }
    {
        int ip = tid >> 4, o = tid & 15;
        s_b2p[tid] = pack2(b2[ip * 32 + o], b2[ip * 32 + 16 + o]);
        s_w1[tid] = w1[tid];
    }
    if (tid < 32) s_b1[tid] = b1[tid];
    __syncthreads();

    int warp = tid >> 5, lane = tid & 31;
    int sub = lane >> 4, o = lane & 15;
    u64* sh = s_hA + warp * 132;
    u64* sx = s_xA + warp * 64;

    const long NG = N_EDGES / 4;
    const long stride = (long)EDGE_GRID * 8;

    for (long g = (long)blockIdx.x * 8 + warp; g < NG; g += stride) {
        long e0 = g * 4;
        int dsts[2];
#pragma unroll
        for (int t2 = 0; t2 < 2; t2++)
            dsts[t2] = __ldg(ei + N_EDGES + e0 + sub * 2 + t2);
        // cooperative h1-gather (relu fused): 4 edges * 16 u64 = 64 words
#pragma unroll
        for (int j = 0; j < 2; j++) {
            int w = lane + 32 * j;
            int e = w >> 4, ip = w & 15;
            int src = __ldg(ei + e0 + e);
            sx[w] = relu2(__ldg((const u64*)g_buf1 + (long)src * 16 + ip));
        }
        // edge-MLP
#pragma unroll
        for (int e = 0; e < 4; e++) {
            const float4* ear = (const float4*)(ea + (e0 + e) * 8);
            float4 a0 = __ldg(ear), a1 = __ldg(ear + 1);
            float acc = s_b1[lane];
            acc = fmaf(a0.x, s_w1[0 * 32 + lane], acc);
            acc = fmaf(a0.y, s_w1[1 * 32 + lane], acc);
            acc = fmaf(a0.z, s_w1[2 * 32 + lane], acc);
            acc = fmaf(a0.w, s_w1[3 * 32 + lane], acc);
            acc = fmaf(a1.x, s_w1[4 * 32 + lane], acc);
            acc = fmaf(a1.y, s_w1[5 * 32 + lane], acc);
            acc = fmaf(a1.z, s_w1[6 * 32 + lane], acc);
            acc = fmaf(a1.w, s_w1[7 * 32 + lane], acc);
            acc = fmaxf(acc, 0.f);
            sh[e * 33 + lane] = pack2(acc, acc);
        }
        __syncwarp();

        // mainloop
        u64 acc[2][16];
#pragma unroll
        for (int ip = 0; ip < 16; ip++) {
            u64 b = s_b2p[ip * 16 + o];
#pragma unroll
            for (int t2 = 0; t2 < 2; t2++) acc[t2][ip] = b;
        }
#pragma unroll 4
        for (int k = 0; k < 32; k++) {
            u64 h[2];
#pragma unroll
            for (int t2 = 0; t2 < 2; t2++) h[t2] = sh[(sub * 2 + t2) * 33 + k];
            const u64* wr = s_w2p + k * 256 + o;
#pragma unroll
            for (int ip = 0; ip < 16; ip++) {
                u64 w = wr[ip * 16];
#pragma unroll
                for (int t2 = 0; t2 < 2; t2++) acc[t2][ip] = fma2(h[t2], w, acc[t2][ip]);
            }
        }
        __syncwarp();

        // epilogue
#pragma unroll
        for (int t2 = 0; t2 < 2; t2++) {
            int e = sub * 2 + t2;
            u64 s = 0ull;
#pragma unroll
            for (int ip = 0; ip < 16; ip++) s = fma2(sx[e * 16 + ip], acc[t2][ip], s);
            atomicAdd(&g_buf2[(long)dsts[t2] * 16 + o], hadd2(s));
        }
        __syncwarp();  // protect sx before next iteration's overwrite
    }
}

// ---------------------------------------------------------------------------
// K6a: zero pooled buffer
// ---------------------------------------------------------------------------
__global__ void zero_pool(void) {
    int t = blockIdx.x * blockDim.x + threadIdx.x;
    if (t < N_GRAPHS * 16) g_pool[t] = 0.f;
}

// ---------------------------------------------------------------------------
// K6: relu(agg2) + global_add_pool via per-block shared accumulation
// ---------------------------------------------------------------------------
__global__ void pool_kernel(const int* __restrict__ batch) {
    __shared__ float sg[N_GRAPHS * 16];
    int tid = threadIdx.x;
    for (int i = tid; i < N_GRAPHS * 16; i += blockDim.x) sg[i] = 0.f;
    __syncthreads();
    int t = blockIdx.x * blockDim.x + tid;
    int stride = gridDim.x * blockDim.x;
    for (int n = t; n < N_NODES; n += stride) {
        int b = batch[n];
        const float* r = g_buf2 + n * 16;
#pragma unroll
        for (int f = 0; f < 16; f++)
            atomicAdd(&sg[b * 16 + f], fmaxf(r[f], 0.f));
    }
    __syncthreads();
    for (int i = tid; i < N_GRAPHS * 16; i += blockDim.x)
        if (sg[i] != 0.f) atomicAdd(&g_pool[i], sg[i]);
}

// ---------------------------------------------------------------------------
// K7: head — per-graph MLP
// ---------------------------------------------------------------------------
__global__ void head_kernel(const float* __restrict__ fc1_w,
                            const float* __restrict__ fc1_b,
                            const float* __restrict__ out_w,
                            const float* __restrict__ out_b,
                            float* __restrict__ out) {
    int t = threadIdx.x;
    if (t >= N_GRAPHS) return;
    const float* gr = g_pool + t * 16;
    float r = out_b[0];
#pragma unroll
    for (int o = 0; o < 32; o++) {
        float acc = fc1_b[o];
#pragma unroll
        for (int i = 0; i < 16; i++) acc = fmaf(gr[i], fc1_w[i * 32 + o], acc);
        r = fmaf(fmaxf(acc, 0.f), out_w[o], r);
    }
    out[t] = r;
}

// ---------------------------------------------------------------------------
extern "C" void kernel_launch(void* const* d_in, const int* in_sizes, int n_in,
                              void* d_out, int out_size) {
    const float* x        = (const float*)d_in[0];
    const int*   ei       = (const int*)  d_in[1];
    const float* ea       = (const float*)d_in[2];
    const int*   batch    = (const int*)  d_in[3];
    const float* c1_w1    = (const float*)d_in[4];
    const float* c1_b1    = (const float*)d_in[5];
    const float* c1_w2    = (const float*)d_in[6];
    const float* c1_b2    = (const float*)d_in[7];
    const float* c1_root  = (const float*)d_in[8];
    const float* c1_bias  = (const float*)d_in[9];
    const float* c2_w1    = (const float*)d_in[10];
    const float* c2_b1    = (const float*)d_in[11];
    const float* c2_w2    = (const float*)d_in[12];
    const float* c2_b2    = (const float*)d_in[13];
    const float* c2_root  = (const float*)d_in[14];
    const float* c2_bias  = (const float*)d_in[15];
    const float* fc1_w    = (const float*)d_in[16];
    const float* fc1_b    = (const float*)d_in[17];
    const float* out_w    = (const float*)d_in[18];
    const float* out_b    = (const float*)d_in[19];
    float* out = (float*)d_out;

    const int smem_e1 = 9904 * 8;    // 79232 B (x2 CTAs = 158464 <= 228K)
    const int smem_e2 = 10160 * 8;   // 81280 B (x2 CTAs = 162560 <= 228K)
    cudaFuncSetAttribute(edge1, cudaFuncAttributeMaxDynamicSharedMemorySize, smem_e1);
    cudaFuncSetAttribute(edge2, cudaFuncAttributeMaxDynamicSharedMemorySize, smem_e2);

    // conv1
    node_init1<<<(N_NODES * 32 + 255) / 256, 256>>>(x, c1_root, c1_bias);
    edge1<<<EDGE_GRID, 256, smem_e1>>>(x, ei, ea, c1_w1, c1_b1, c1_w2, c1_b2);
    // conv2 (relu fused into consumers of g_buf1)
    node_init2<<<(N_NODES * 16 + 255) / 256, 256>>>(c2_root, c2_bias);
    edge2<<<EDGE_GRID, 256, smem_e2>>>(ei, ea, c2_w1, c2_b1, c2_w2, c2_b2);
    // pool + head
    zero_pool<<<1, 1024>>>();
    pool_kernel<<<120, 256>>>(batch);
    head_kernel<<<1, 64>>>(fc1_w, fc1_b, out_w, out_b, out);
}

// round 12
// speedup vs baseline: 1.4866x; 1.4866x over previous
#include <cuda_runtime.h>
#include <cuda_bf16.h>

#define N_NODES 50000
#define N_EDGES 400000
#define N_GRAPHS 64
#define Y1_STRIDE 1056   // 33 rows * 32 cols (row 32 = bias term)
#define Y2_STRIDE 528    // 33 rows * 16 cols

// Scratch (device globals; no allocation allowed)
__device__ float g_Y[N_NODES * Y1_STRIDE];   // 211.2 MB, reused for Y2
__device__ float g_buf1[N_NODES * 32];       // conv1 accumulator (pre-relu)
__device__ float g_buf2[N_NODES * 16];       // conv2 accumulator
__device__ float g_pool[N_GRAPHS * 16];      // pooled graph features

// ---------------------------------------------------------------------------
// K1: agg1[n,o] = c1_bias[o] + sum_i x[n,i] * c1_root[i,o]
// ---------------------------------------------------------------------------
__global__ void node_init1(const float* __restrict__ x,
                           const float* __restrict__ root,
                           const float* __restrict__ bias) {
    int t = blockIdx.x * blockDim.x + threadIdx.x;
    if (t >= N_NODES * 32) return;
    int n = t >> 5, o = t & 31;
    const float* xr = x + n * 16;
    float acc = bias[o];
#pragma unroll
    for (int i = 0; i < 16; i++) acc = fmaf(xr[i], root[i * 32 + o], acc);
    g_buf1[t] = acc;
}

// ---------------------------------------------------------------------------
// Y1: Y[n,k,o] = sum_i x[n,i] * w2[k, i*32+o]   (k<32; row 32 = b2 term)
// Block = 8 nodes, 256 threads; thread owns (kslot, o), 4 k's.
// ---------------------------------------------------------------------------
__global__ void y1_kernel(const float* __restrict__ x,
                          const float* __restrict__ w2,
                          const float* __restrict__ b2) {
    __shared__ float sx[8 * 16];
    int tid = threadIdx.x;
    int o = tid & 31, kslot = tid >> 5;     // kslot 0..7
    long n0 = (long)blockIdx.x * 8;
    if (tid < 128) sx[tid] = x[n0 * 16 + tid];
    float wr[4][16];
#pragma unroll
    for (int s = 0; s < 4; s++) {
        int k = kslot + s * 8;
#pragma unroll
        for (int i = 0; i < 16; i++) wr[s][i] = __ldg(w2 + k * 512 + i * 32 + o);
    }
    float br[16];
    if (kslot == 0) {
#pragma unroll
        for (int i = 0; i < 16; i++) br[i] = __ldg(b2 + i * 32 + o);
    }
    __syncthreads();
#pragma unroll 1
    for (int n = 0; n < 8; n++) {
        float acc[4] = {0.f, 0.f, 0.f, 0.f};
        float accb = 0.f;
#pragma unroll
        for (int i = 0; i < 16; i++) {
            float v = sx[n * 16 + i];
#pragma unroll
            for (int s = 0; s < 4; s++) acc[s] = fmaf(v, wr[s][i], acc[s]);
            if (kslot == 0) accb = fmaf(v, br[i], accb);
        }
        float* out = g_Y + (n0 + n) * Y1_STRIDE;
#pragma unroll
        for (int s = 0; s < 4; s++) out[(kslot + s * 8) * 32 + o] = acc[s];
        if (kslot == 0) out[1024 + o] = accb;
    }
}

// ---------------------------------------------------------------------------
// K2: conv1 edge kernel. Warp = 1 edge; lane = k for h, = o for contraction.
// msg[e,o] = Yb[src,o] + sum_k h[e,k] * Y[src,k,o]; atomic scatter to dst.
// ---------------------------------------------------------------------------
__global__ __launch_bounds__(256) void edge1(
    const int* __restrict__ ei, const float* __restrict__ ea,
    const float* __restrict__ w1, const float* __restrict__ b1) {
    __shared__ float s_w1[256], s_b1[32];
    int tid = threadIdx.x, lane = tid & 31, warp = tid >> 5;
    s_w1[tid] = w1[tid];
    if (tid < 32) s_b1[tid] = b1[tid];
    __syncthreads();

    long e = (long)blockIdx.x * 8 + warp;   // grid*8 == N_EDGES exactly
    int src = __ldg(ei + e);
    int dst = __ldg(ei + N_EDGES + e);
    const float4* ear = (const float4*)(ea + e * 8);
    float4 a0 = __ldg(ear), a1 = __ldg(ear + 1);
    float h = s_b1[lane];
    h = fmaf(a0.x, s_w1[0 * 32 + lane], h);
    h = fmaf(a0.y, s_w1[1 * 32 + lane], h);
    h = fmaf(a0.z, s_w1[2 * 32 + lane], h);
    h = fmaf(a0.w, s_w1[3 * 32 + lane], h);
    h = fmaf(a1.x, s_w1[4 * 32 + lane], h);
    h = fmaf(a1.y, s_w1[5 * 32 + lane], h);
    h = fmaf(a1.z, s_w1[6 * 32 + lane], h);
    h = fmaf(a1.w, s_w1[7 * 32 + lane], h);
    h = fmaxf(h, 0.f);

    const float* Yr = g_Y + (long)src * Y1_STRIDE + lane;
    float msg = __ldg(Yr + 1024);           // bias row (k=32)
#pragma unroll
    for (int k = 0; k < 32; k++)
        msg = fmaf(__shfl_sync(0xffffffffu, h, k), __ldg(Yr + k * 32), msg);
    atomicAdd(&g_buf1[(long)dst * 32 + lane], msg);
}

// ---------------------------------------------------------------------------
// K4: agg2[n,o] = c2_bias[o] + sum_i relu(agg1[n,i]) * c2_root[i,o]
// ---------------------------------------------------------------------------
__global__ void node_init2(const float* __restrict__ root,
                           const float* __restrict__ bias) {
    int t = blockIdx.x * blockDim.x + threadIdx.x;
    if (t >= N_NODES * 16) return;
    int n = t >> 4, o = t & 15;
    const float* xr = g_buf1 + n * 32;
    float acc = bias[o];
#pragma unroll
    for (int i = 0; i < 32; i++) acc = fmaf(fmaxf(xr[i], 0.f), root[i * 16 + o], acc);
    g_buf2[t] = acc;
}

// ---------------------------------------------------------------------------
// Y2: Y[n,k,o] = sum_i relu(h1[n,i]) * w2[k, i*16+o]  (k<32; row 32 = b2 term)
// Block = 8 nodes, 256 threads; thread owns (kb, o), 2 k's.
// ---------------------------------------------------------------------------
__global__ void y2_kernel(const float* __restrict__ w2,
                          const float* __restrict__ b2) {
    __shared__ float sx[8 * 32];
    int tid = threadIdx.x;
    int o = tid & 15, kb = tid >> 4;        // kb 0..15
    long n0 = (long)blockIdx.x * 8;
    sx[tid] = fmaxf(g_buf1[n0 * 32 + tid], 0.f);
    float wr[2][32];
#pragma unroll
    for (int s = 0; s < 2; s++) {
        int k = kb + s * 16;
#pragma unroll
        for (int i = 0; i < 32; i++) wr[s][i] = __ldg(w2 + k * 512 + i * 16 + o);
    }
    float br[32];
    if (kb == 0) {
#pragma unroll
        for (int i = 0; i < 32; i++) br[i] = __ldg(b2 + i * 16 + o);
    }
    __syncthreads();
#pragma unroll 1
    for (int n = 0; n < 8; n++) {
        float acc0 = 0.f, acc1 = 0.f, accb = 0.f;
#pragma unroll
        for (int i = 0; i < 32; i++) {
            float v = sx[n * 32 + i];
            acc0 = fmaf(v, wr[0][i], acc0);
            acc1 = fmaf(v, wr[1][i], acc1);
            if (kb == 0) accb = fmaf(v, br[i], accb);
        }
        float* out = g_Y + (n0 + n) * Y2_STRIDE;
        out[kb * 16 + o] = acc0;
        out[(kb + 16) * 16 + o] = acc1;
        if (kb == 0) out[512 + o] = accb;
    }
}

// ---------------------------------------------------------------------------
// K5: conv2 edge kernel. Half-warp = 1 edge (o<16); warp = 2 edges.
// ---------------------------------------------------------------------------
__global__ __launch_bounds__(256) void edge2(
    const int* __restrict__ ei, const float* __restrict__ ea,
    const float* __restrict__ w1, const float* __restrict__ b1) {
    __shared__ float s_w1[256], s_b1[32];
    int tid = threadIdx.x, lane = tid & 31, warp = tid >> 5;
    s_w1[tid] = w1[tid];
    if (tid < 32) s_b1[tid] = b1[tid];
    __syncthreads();

    int sub = lane >> 4, o = lane & 15;
    long e0 = ((long)blockIdx.x * 8 + warp) * 2;   // grid*16 == N_EDGES

    // h for both edges of this warp (lane = k)
    float hA, hB;
    {
        const float4* ear = (const float4*)(ea + e0 * 8);
        float4 a0 = __ldg(ear), a1 = __ldg(ear + 1);
        float h = s_b1[lane];
        h = fmaf(a0.x, s_w1[0 * 32 + lane], h);
        h = fmaf(a0.y, s_w1[1 * 32 + lane], h);
        h = fmaf(a0.z, s_w1[2 * 32 + lane], h);
        h = fmaf(a0.w, s_w1[3 * 32 + lane], h);
        h = fmaf(a1.x, s_w1[4 * 32 + lane], h);
        h = fmaf(a1.y, s_w1[5 * 32 + lane], h);
        h = fmaf(a1.z, s_w1[6 * 32 + lane], h);
        h = fmaf(a1.w, s_w1[7 * 32 + lane], h);
        hA = fmaxf(h, 0.f);
    }
    {
        const float4* ear = (const float4*)(ea + (e0 + 1) * 8);
        float4 a0 = __ldg(ear), a1 = __ldg(ear + 1);
        float h = s_b1[lane];
        h = fmaf(a0.x, s_w1[0 * 32 + lane], h);
        h = fmaf(a0.y, s_w1[1 * 32 + lane], h);
        h = fmaf(a0.z, s_w1[2 * 32 + lane], h);
        h = fmaf(a0.w, s_w1[3 * 32 + lane], h);
        h = fmaf(a1.x, s_w1[4 * 32 + lane], h);
        h = fmaf(a1.y, s_w1[5 * 32 + lane], h);
        h = fmaf(a1.z, s_w1[6 * 32 + lane], h);
        h = fmaf(a1.w, s_w1[7 * 32 + lane], h);
        hB = fmaxf(h, 0.f);
    }

    long eM = e0 + sub;
    int src = __ldg(ei + eM);
    int dst = __ldg(ei + N_EDGES + eM);
    const float* Yr = g_Y + (long)src * Y2_STRIDE + o;
    float msg = __ldg(Yr + 512);            // bias row (k=32)
#pragma unroll
    for (int k = 0; k < 32; k++) {
        float ha = __shfl_sync(0xffffffffu, hA, k);
        float hb = __shfl_sync(0xffffffffu, hB, k);
        msg = fmaf(sub ? hb : ha, __ldg(Yr + k * 16), msg);
    }
    atomicAdd(&g_buf2[(long)dst * 16 + o], msg);
}

// ---------------------------------------------------------------------------
// K6a: zero pooled buffer
// ---------------------------------------------------------------------------
__global__ void zero_pool(void) {
    int t = blockIdx.x * blockDim.x + threadIdx.x;
    if (t < N_GRAPHS * 16) g_pool[t] = 0.f;
}

// ---------------------------------------------------------------------------
// K6: relu(agg2) + global_add_pool via per-block shared accumulation
// ---------------------------------------------------------------------------
__global__ void pool_kernel(const int* __restrict__ batch) {
    __shared__ float sg[N_GRAPHS * 16];
    int tid = threadIdx.x;
    for (int i = tid; i < N_GRAPHS * 16; i += blockDim.x) sg[i] = 0.f;
    __syncthreads();
    int t = blockIdx.x * blockDim.x + tid;
    int stride = gridDim.x * blockDim.x;
    for (int n = t; n < N_NODES; n += stride) {
        int b = batch[n];
        const float* r = g_buf2 + n * 16;
#pragma unroll
        for (int f = 0; f < 16; f++)
            atomicAdd(&sg[b * 16 + f], fmaxf(r[f], 0.f));
    }
    __syncthreads();
    for (int i = tid; i < N_GRAPHS * 16; i += blockDim.x)
        if (sg[i] != 0.f) atomicAdd(&g_pool[i], sg[i]);
}

// ---------------------------------------------------------------------------
// K7: head — per-graph MLP
// ---------------------------------------------------------------------------
__global__ void head_kernel(const float* __restrict__ fc1_w,
                            const float* __restrict__ fc1_b,
                            const float* __restrict__ out_w,
                            const float* __restrict__ out_b,
                            float* __restrict__ out) {
    int t = threadIdx.x;
    if (t >= N_GRAPHS) return;
    const float* gr = g_pool + t * 16;
    float r = out_b[0];
#pragma unroll
    for (int o = 0; o < 32; o++) {
        float acc = fc1_b[o];
#pragma unroll
        for (int i = 0; i < 16; i++) acc = fmaf(gr[i], fc1_w[i * 32 + o], acc);
        r = fmaf(fmaxf(acc, 0.f), out_w[o], r);
    }
    out[t] = r;
}

// ---------------------------------------------------------------------------
extern "C" void kernel_launch(void* const* d_in, const int* in_sizes, int n_in,
                              void* d_out, int out_size) {
    const float* x        = (const float*)d_in[0];
    const int*   ei       = (const int*)  d_in[1];
    const float* ea       = (const float*)d_in[2];
    const int*   batch    = (const int*)  d_in[3];
    const float* c1_w1    = (const float*)d_in[4];
    const float* c1_b1    = (const float*)d_in[5];
    const float* c1_w2    = (const float*)d_in[6];
    const float* c1_b2    = (const float*)d_in[7];
    const float* c1_root  = (const float*)d_in[8];
    const float* c1_bias  = (const float*)d_in[9];
    const float* c2_w1    = (const float*)d_in[10];
    const float* c2_b1    = (const float*)d_in[11];
    const float* c2_w2    = (const float*)d_in[12];
    const float* c2_b2    = (const float*)d_in[13];
    const float* c2_root  = (const float*)d_in[14];
    const float* c2_bias  = (const float*)d_in[15];
    const float* fc1_w    = (const float*)d_in[16];
    const float* fc1_b    = (const float*)d_in[17];
    const float* out_w    = (const float*)d_in[18];
    const float* out_b    = (const float*)d_in[19];
    float* out = (float*)d_out;

    // conv1
    node_init1<<<(N_NODES * 32 + 255) / 256, 256>>>(x, c1_root, c1_bias);
    y1_kernel<<<N_NODES / 8, 256>>>(x, c1_w2, c1_b2);
    edge1<<<N_EDGES / 8, 256>>>(ei, ea, c1_w1, c1_b1);
    // conv2 (relu fused into consumers of g_buf1)
    node_init2<<<(N_NODES * 16 + 255) / 256, 256>>>(c2_root, c2_bias);
    y2_kernel<<<N_NODES / 8, 256>>>(c2_w2, c2_b2);
    edge2<<<N_EDGES / 16, 256>>>(ei, ea, c2_w1, c2_b1);
    // pool + head
    zero_pool<<<1, 1024>>>();
    pool_kernel<<<120, 256>>>(batch);
    head_kernel<<<1, 64>>>(fc1_w, fc1_b, out_w, out_b, out);
}

// round 14
// speedup vs baseline: 1.5120x; 1.0171x over previous
#include <cuda_runtime.h>
#include <cuda_bf16.h>

#define N_NODES 50000
#define N_EDGES 400000
#define N_GRAPHS 64
#define Y1_STRIDE 1056   // 33 rows * 32 cols (row 32 = bias term)
#define Y2_STRIDE 528    // 33 rows * 16 cols

// Scratch (device globals; no allocation allowed)
__device__ float g_Y[N_NODES * Y1_STRIDE];   // 211.2 MB, reused for Y2
__device__ float g_buf1[N_NODES * 32];       // conv1 accumulator (pre-relu)
__device__ float g_buf2[N_NODES * 16];       // conv2 accumulator
__device__ float g_pool[N_GRAPHS * 16];      // pooled graph features
__device__ int   g_cnt[N_NODES];             // src histogram
__device__ int   g_off[N_NODES];             // exclusive prefix (consumed by scatter)
__device__ int   g_perm[N_EDGES];            // edges sorted by src

// ---------------------------------------------------------------------------
// S0: zero histogram + pool
// ---------------------------------------------------------------------------
__global__ void zero_misc(void) {
    int t = blockIdx.x * blockDim.x + threadIdx.x;
    if (t < N_NODES) g_cnt[t] = 0;
    if (t < N_GRAPHS * 16) g_pool[t] = 0.f;
}

// ---------------------------------------------------------------------------
// S1: histogram of src
// ---------------------------------------------------------------------------
__global__ void hist_kernel(const int* __restrict__ ei) {
    int e = blockIdx.x * blockDim.x + threadIdx.x;
    if (e < N_EDGES) atomicAdd(&g_cnt[__ldg(ei + e)], 1);
}

// ---------------------------------------------------------------------------
// S2: single-block exclusive scan (1024 threads, 49 nodes/thread)
// ---------------------------------------------------------------------------
__global__ void scan_kernel(void) {
    __shared__ int ssum[1024];
    const int CH = 49;                 // 1024*49 = 50176 >= N_NODES
    int t = threadIdx.x;
    int base = t * CH;
    int local[CH];
    int s = 0;
#pragma unroll
    for (int i = 0; i < CH; i++) {
        int idx = base + i;
        int v = (idx < N_NODES) ? g_cnt[idx] : 0;
        local[i] = v; s += v;
    }
    ssum[t] = s;
    __syncthreads();
    for (int d = 1; d < 1024; d <<= 1) {
        int v = (t >= d) ? ssum[t - d] : 0;
        __syncthreads();
        ssum[t] += v;
        __syncthreads();
    }
    int off = (t == 0) ? 0 : ssum[t - 1];
#pragma unroll
    for (int i = 0; i < CH; i++) {
        int idx = base + i;
        if (idx < N_NODES) g_off[idx] = off;
        off += local[i];
    }
}

// ---------------------------------------------------------------------------
// S3: scatter edge ids into src-sorted permutation (consumes g_off)
// ---------------------------------------------------------------------------
__global__ void scatter_kernel(const int* __restrict__ ei) {
    int e = blockIdx.x * blockDim.x + threadIdx.x;
    if (e >= N_EDGES) return;
    int pos = atomicAdd(&g_off[__ldg(ei + e)], 1);
    g_perm[pos] = e;
}

// ---------------------------------------------------------------------------
// K1: agg1[n,o] = c1_bias[o] + sum_i x[n,i] * c1_root[i,o]
// ---------------------------------------------------------------------------
__global__ void node_init1(const float* __restrict__ x,
                           const float* __restrict__ root,
                           const float* __restrict__ bias) {
    int t = blockIdx.x * blockDim.x + threadIdx.x;
    if (t >= N_NODES * 32) return;
    int n = t >> 5, o = t & 31;
    const float* xr = x + n * 16;
    float acc = bias[o];
#pragma unroll
    for (int i = 0; i < 16; i++) acc = fmaf(xr[i], root[i * 32 + o], acc);
    g_buf1[t] = acc;
}

// ---------------------------------------------------------------------------
// Y1: Y[n,k,o] = sum_i x[n,i] * w2[k, i*32+o]   (k<32; row 32 = b2 term)
// ---------------------------------------------------------------------------
__global__ void y1_kernel(const float* __restrict__ x,
                          const float* __restrict__ w2,
                          const float* __restrict__ b2) {
    __shared__ float sx[8 * 16];
    int tid = threadIdx.x;
    int o = tid & 31, kslot = tid >> 5;
    long n0 = (long)blockIdx.x * 8;
    if (tid < 128) sx[tid] = x[n0 * 16 + tid];
    float wr[4][16];
#pragma unroll
    for (int s = 0; s < 4; s++) {
        int k = kslot + s * 8;
#pragma unroll
        for (int i = 0; i < 16; i++) wr[s][i] = __ldg(w2 + k * 512 + i * 32 + o);
    }
    float br[16];
    if (kslot == 0) {
#pragma unroll
        for (int i = 0; i < 16; i++) br[i] = __ldg(b2 + i * 32 + o);
    }
    __syncthreads();
#pragma unroll 1
    for (int n = 0; n < 8; n++) {
        float acc[4] = {0.f, 0.f, 0.f, 0.f};
        float accb = 0.f;
#pragma unroll
        for (int i = 0; i < 16; i++) {
            float v = sx[n * 16 + i];
#pragma unroll
            for (int s = 0; s < 4; s++) acc[s] = fmaf(v, wr[s][i], acc[s]);
            if (kslot == 0) accb = fmaf(v, br[i], accb);
        }
        float* out = g_Y + (n0 + n) * Y1_STRIDE;
#pragma unroll
        for (int s = 0; s < 4; s++) out[(kslot + s * 8) * 32 + o] = acc[s];
        if (kslot == 0) out[1024 + o] = accb;
    }
}

// ---------------------------------------------------------------------------
// K2: conv1 edge kernel. Warp = 1 src-sorted edge; consecutive warps share
// src -> Y row hits L1. msg = Yb[src] + sum_k h[k]*Y[src,k,:]; atomic to dst.
// ---------------------------------------------------------------------------
__global__ __launch_bounds__(256) void edge1(
    const int* __restrict__ ei, const float* __restrict__ ea,
    const float* __restrict__ w1, const float* __restrict__ b1) {
    __shared__ float s_w1[256], s_b1[32];
    int tid = threadIdx.x, lane = tid & 31, warp = tid >> 5;
    s_w1[tid] = w1[tid];
    if (tid < 32) s_b1[tid] = b1[tid];
    __syncthreads();

    long e = __ldg(g_perm + (long)blockIdx.x * 8 + warp);
    int src = __ldg(ei + e);
    int dst = __ldg(ei + N_EDGES + e);
    const float4* ear = (const float4*)(ea + e * 8);
    float4 a0 = __ldg(ear), a1 = __ldg(ear + 1);
    float h = s_b1[lane];
    h = fmaf(a0.x, s_w1[0 * 32 + lane], h);
    h = fmaf(a0.y, s_w1[1 * 32 + lane], h);
    h = fmaf(a0.z, s_w1[2 * 32 + lane], h);
    h = fmaf(a0.w, s_w1[3 * 32 + lane], h);
    h = fmaf(a1.x, s_w1[4 * 32 + lane], h);
    h = fmaf(a1.y, s_w1[5 * 32 + lane], h);
    h = fmaf(a1.z, s_w1[6 * 32 + lane], h);
    h = fmaf(a1.w, s_w1[7 * 32 + lane], h);
    h = fmaxf(h, 0.f);

    const float* Yr = g_Y + (long)src * Y1_STRIDE + lane;
    float msg = __ldg(Yr + 1024);
#pragma unroll
    for (int k = 0; k < 32; k++)
        msg = fmaf(__shfl_sync(0xffffffffu, h, k), __ldg(Yr + k * 32), msg);
    atomicAdd(&g_buf1[(long)dst * 32 + lane], msg);
}

// ---------------------------------------------------------------------------
// K4: agg2[n,o] = c2_bias[o] + sum_i relu(agg1[n,i]) * c2_root[i,o]
// ---------------------------------------------------------------------------
__global__ void node_init2(const float* __restrict__ root,
                           const float* __restrict__ bias) {
    int t = blockIdx.x * blockDim.x + threadIdx.x;
    if (t >= N_NODES * 16) return;
    int n = t >> 4, o = t & 15;
    const float* xr = g_buf1 + n * 32;
    float acc = bias[o];
#pragma unroll
    for (int i = 0; i < 32; i++) acc = fmaf(fmaxf(xr[i], 0.f), root[i * 16 + o], acc);
    g_buf2[t] = acc;
}

// ---------------------------------------------------------------------------
// Y2: Y[n,k,o] = sum_i relu(h1[n,i]) * w2[k, i*16+o]  (k<32; row 32 = b2)
// ---------------------------------------------------------------------------
__global__ void y2_kernel(const float* __restrict__ w2,
                          const float* __restrict__ b2) {
    __shared__ float sx[8 * 32];
    int tid = threadIdx.x;
    int o = tid & 15, kb = tid >> 4;
    long n0 = (long)blockIdx.x * 8;
    sx[tid] = fmaxf(g_buf1[n0 * 32 + tid], 0.f);
    float wr[2][32];
#pragma unroll
    for (int s = 0; s < 2; s++) {
        int k = kb + s * 16;
#pragma unroll
        for (int i = 0; i < 32; i++) wr[s][i] = __ldg(w2 + k * 512 + i * 16 + o);
    }
    float br[32];
    if (kb == 0) {
#pragma unroll
        for (int i = 0; i < 32; i++) br[i] = __ldg(b2 + i * 16 + o);
    }
    __syncthreads();
#pragma unroll 1
    for (int n = 0; n < 8; n++) {
        float acc0 = 0.f, acc1 = 0.f, accb = 0.f;
#pragma unroll
        for (int i = 0; i < 32; i++) {
            float v = sx[n * 32 + i];
            acc0 = fmaf(v, wr[0][i], acc0);
            acc1 = fmaf(v, wr[1][i], acc1);
            if (kb == 0) accb = fmaf(v, br[i], accb);
        }
        float* out = g_Y + (n0 + n) * Y2_STRIDE;
        out[kb * 16 + o] = acc0;
        out[(kb + 16) * 16 + o] = acc1;
        if (kb == 0) out[512 + o] = accb;
    }
}

// ---------------------------------------------------------------------------
// K5: conv2 edge kernel. Half-warp = 1 src-sorted edge; warp = 2 edges.
// ---------------------------------------------------------------------------
__global__ __launch_bounds__(256) void edge2(
    const int* __restrict__ ei, const float* __restrict__ ea,
    const float* __restrict__ w1, const float* __restrict__ b1) {
    __shared__ float s_w1[256], s_b1[32];
    int tid = threadIdx.x, lane = tid & 31, warp = tid >> 5;
    s_w1[tid] = w1[tid];
    if (tid < 32) s_b1[tid] = b1[tid];
    __syncthreads();

    int sub = lane >> 4, o = lane & 15;
    long p0 = ((long)blockIdx.x * 8 + warp) * 2;
    long eA = __ldg(g_perm + p0);
    long eB = __ldg(g_perm + p0 + 1);

    float hA, hB;
    {
        const float4* ear = (const float4*)(ea + eA * 8);
        float4 a0 = __ldg(ear), a1 = __ldg(ear + 1);
        float h = s_b1[lane];
        h = fmaf(a0.x, s_w1[0 * 32 + lane], h);
        h = fmaf(a0.y, s_w1[1 * 32 + lane], h);
        h = fmaf(a0.z, s_w1[2 * 32 + lane], h);
        h = fmaf(a0.w, s_w1[3 * 32 + lane], h);
        h = fmaf(a1.x, s_w1[4 * 32 + lane], h);
        h = fmaf(a1.y, s_w1[5 * 32 + lane], h);
        h = fmaf(a1.z, s_w1[6 * 32 + lane], h);
        h = fmaf(a1.w, s_w1[7 * 32 + lane], h);
        hA = fmaxf(h, 0.f);
    }
    {
        const float4* ear = (const float4*)(ea + eB * 8);
        float4 a0 = __ldg(ear), a1 = __ldg(ear + 1);
        float h = s_b1[lane];
        h = fmaf(a0.x, s_w1[0 * 32 + lane], h);
        h = fmaf(a0.y, s_w1[1 * 32 + lane], h);
        h = fmaf(a0.z, s_w1[2 * 32 + lane], h);
        h = fmaf(a0.w, s_w1[3 * 32 + lane], h);
        h = fmaf(a1.x, s_w1[4 * 32 + lane], h);
        h = fmaf(a1.y, s_w1[5 * 32 + lane], h);
        h = fmaf(a1.z, s_w1[6 * 32 + lane], h);
        h = fmaf(a1.w, s_w1[7 * 32 + lane], h);
        hB = fmaxf(h, 0.f);
    }

    long eM = sub ? eB : eA;
    int src = __ldg(ei + eM);
    int dst = __ldg(ei + N_EDGES + eM);
    const float* Yr = g_Y + (long)src * Y2_STRIDE + o;
    float msg = __ldg(Yr + 512);
#pragma unroll
    for (int k = 0; k < 32; k++) {
        float ha = __shfl_sync(0xffffffffu, hA, k);
        float hb = __shfl_sync(0xffffffffu, hB, k);
        msg = fmaf(sub ? hb : ha, __ldg(Yr + k * 16), msg);
    }
    atomicAdd(&g_buf2[(long)dst * 16 + o], msg);
}

// ---------------------------------------------------------------------------
// K6: relu(agg2) + global_add_pool via per-block shared accumulation
// ---------------------------------------------------------------------------
__global__ void pool_kernel(const int* __restrict__ batch) {
    __shared__ float sg[N_GRAPHS * 16];
    int tid = threadIdx.x;
    for (int i = tid; i < N_GRAPHS * 16; i += blockDim.x) sg[i] = 0.f;
    __syncthreads();
    int t = blockIdx.x * blockDim.x + tid;
    int stride = gridDim.x * blockDim.x;
    for (int n = t; n < N_NODES; n += stride) {
        int b = batch[n];
        const float* r = g_buf2 + n * 16;
#pragma unroll
        for (int f = 0; f < 16; f++)
            atomicAdd(&sg[b * 16 + f], fmaxf(r[f], 0.f));
    }
    __syncthreads();
    for (int i = tid; i < N_GRAPHS * 16; i += blockDim.x)
        if (sg[i] != 0.f) atomicAdd(&g_pool[i], sg[i]);
}

// ---------------------------------------------------------------------------
// K7: head — per-graph MLP
// ---------------------------------------------------------------------------
__global__ void head_kernel(const float* __restrict__ fc1_w,
                            const float* __restrict__ fc1_b,
                            const float* __restrict__ out_w,
                            const float* __restrict__ out_b,
                            float* __restrict__ out) {
    int t = threadIdx.x;
    if (t >= N_GRAPHS) return;
    const float* gr = g_pool + t * 16;
    float r = out_b[0];
#pragma unroll
    for (int o = 0; o < 32; o++) {
        float acc = fc1_b[o];
#pragma unroll
        for (int i = 0; i < 16; i++) acc = fmaf(gr[i], fc1_w[i * 32 + o], acc);
        r = fmaf(fmaxf(acc, 0.f), out_w[o], r);
    }
    out[t] = r;
}

// ---------------------------------------------------------------------------
extern "C" void kernel_launch(void* const* d_in, const int* in_sizes, int n_in,
                              void* d_out, int out_size) {
    const float* x        = (const float*)d_in[0];
    const int*   ei       = (const int*)  d_in[1];
    const float* ea       = (const float*)d_in[2];
    const int*   batch    = (const int*)  d_in[3];
    const float* c1_w1    = (const float*)d_in[4];
    const float* c1_b1    = (const float*)d_in[5];
    const float* c1_w2    = (const float*)d_in[6];
    const float* c1_b2    = (const float*)d_in[7];
    const float* c1_root  = (const float*)d_in[8];
    const float* c1_bias  = (const float*)d_in[9];
    const float* c2_w1    = (const float*)d_in[10];
    const float* c2_b1    = (const float*)d_in[11];
    const float* c2_w2    = (const float*)d_in[12];
    const float* c2_b2    = (const float*)d_in[13];
    const float* c2_root  = (const float*)d_in[14];
    const float* c2_bias  = (const float*)d_in[15];
    const float* fc1_w    = (const float*)d_in[16];
    const float* fc1_b    = (const float*)d_in[17];
    const float* out_w    = (const float*)d_in[18];
    const float* out_b    = (const float*)d_in[19];
    float* out = (float*)d_out;

    // src-sort (perm reused by both convs)
    zero_misc<<<(N_NODES + 255) / 256, 256>>>();
    hist_kernel<<<(N_EDGES + 255) / 256, 256>>>(ei);
    scan_kernel<<<1, 1024>>>();
    scatter_kernel<<<(N_EDGES + 255) / 256, 256>>>(ei);

    // conv1
    node_init1<<<(N_NODES * 32 + 255) / 256, 256>>>(x, c1_root, c1_bias);
    y1_kernel<<<N_NODES / 8, 256>>>(x, c1_w2, c1_b2);
    edge1<<<N_EDGES / 8, 256>>>(ei, ea, c1_w1, c1_b1);
    // conv2 (relu fused into consumers of g_buf1)
    node_init2<<<(N_NODES * 16 + 255) / 256, 256>>>(c2_root, c2_bias);
    y2_kernel<<<N_NODES / 8, 256>>>(c2_w2, c2_b2);
    edge2<<<N_EDGES / 16, 256>>>(ei, ea, c2_w1, c2_b1);
    // pool + head
    pool_kernel<<<120, 256>>>(batch);
    head_kernel<<<1, 64>>>(fc1_w, fc1_b, out_w, out_b, out);
}

// round 16
// speedup vs baseline: 1.6639x; 1.1004x over previous
#include <cuda_runtime.h>
#include <cuda_bf16.h>

#define N_NODES 50000
#define N_EDGES 400000
#define N_GRAPHS 64
#define Y1_STRIDE 1056   // 33 rows * 32 cols (row 32 = bias term)
#define Y2_STRIDE 528    // 33 rows * 16 cols

// Scratch (device globals; no allocation allowed)
__device__ float g_Y[N_NODES * Y1_STRIDE];   // 211.2 MB, reused for Y2
__device__ float g_buf1[N_NODES * 32];       // conv1 accumulator (pre-relu)
__device__ float g_buf2[N_NODES * 16];       // conv2 accumulator
__device__ float g_pool[N_GRAPHS * 16];      // pooled graph features
__device__ int   g_cnt[N_NODES];             // src histogram (preserved)
__device__ int   g_off[N_NODES];             // post-scatter: END offset per node
__device__ int   g_perm[N_EDGES];            // edges grouped by src

// ---------------------------------------------------------------------------
// S0: zero histogram + pool
// ---------------------------------------------------------------------------
__global__ void zero_misc(void) {
    int t = blockIdx.x * blockDim.x + threadIdx.x;
    if (t < N_NODES) g_cnt[t] = 0;
    if (t < N_GRAPHS * 16) g_pool[t] = 0.f;
}

// ---------------------------------------------------------------------------
// S1: histogram of src
// ---------------------------------------------------------------------------
__global__ void hist_kernel(const int* __restrict__ ei) {
    int e = blockIdx.x * blockDim.x + threadIdx.x;
    if (e < N_EDGES) atomicAdd(&g_cnt[__ldg(ei + e)], 1);
}

// ---------------------------------------------------------------------------
// S2: single-block exclusive scan (1024 threads, 49 nodes/thread)
// ---------------------------------------------------------------------------
__global__ void scan_kernel(void) {
    __shared__ int ssum[1024];
    const int CH = 49;                 // 1024*49 = 50176 >= N_NODES
    int t = threadIdx.x;
    int base = t * CH;
    int local[CH];
    int s = 0;
#pragma unroll
    for (int i = 0; i < CH; i++) {
        int idx = base + i;
        int v = (idx < N_NODES) ? g_cnt[idx] : 0;
        local[i] = v; s += v;
    }
    ssum[t] = s;
    __syncthreads();
    for (int d = 1; d < 1024; d <<= 1) {
        int v = (t >= d) ? ssum[t - d] : 0;
        __syncthreads();
        ssum[t] += v;
        __syncthreads();
    }
    int off = (t == 0) ? 0 : ssum[t - 1];
#pragma unroll
    for (int i = 0; i < CH; i++) {
        int idx = base + i;
        if (idx < N_NODES) g_off[idx] = off;
        off += local[i];
    }
}

// ---------------------------------------------------------------------------
// S3: scatter edge ids grouped by src (g_off becomes END offset per node)
// ---------------------------------------------------------------------------
__global__ void scatter_kernel(const int* __restrict__ ei) {
    int e = blockIdx.x * blockDim.x + threadIdx.x;
    if (e >= N_EDGES) return;
    int pos = atomicAdd(&g_off[__ldg(ei + e)], 1);
    g_perm[pos] = e;
}

// ---------------------------------------------------------------------------
// K1: agg1[n,o] = c1_bias[o] + sum_i x[n,i] * c1_root[i,o]
// ---------------------------------------------------------------------------
__global__ void node_init1(const float* __restrict__ x,
                           const float* __restrict__ root,
                           const float* __restrict__ bias) {
    int t = blockIdx.x * blockDim.x + threadIdx.x;
    if (t >= N_NODES * 32) return;
    int n = t >> 5, o = t & 31;
    const float* xr = x + n * 16;
    float acc = bias[o];
#pragma unroll
    for (int i = 0; i < 16; i++) acc = fmaf(xr[i], root[i * 32 + o], acc);
    g_buf1[t] = acc;
}

// ---------------------------------------------------------------------------
// Y1: Y[n,k,o] = sum_i x[n,i] * w2[k, i*32+o]   (k<32; row 32 = b2 term)
// ---------------------------------------------------------------------------
__global__ void y1_kernel(const float* __restrict__ x,
                          const float* __restrict__ w2,
                          const float* __restrict__ b2) {
    __shared__ float sx[8 * 16];
    int tid = threadIdx.x;
    int o = tid & 31, kslot = tid >> 5;
    long n0 = (long)blockIdx.x * 8;
    if (tid < 128) sx[tid] = x[n0 * 16 + tid];
    float wr[4][16];
#pragma unroll
    for (int s = 0; s < 4; s++) {
        int k = kslot + s * 8;
#pragma unroll
        for (int i = 0; i < 16; i++) wr[s][i] = __ldg(w2 + k * 512 + i * 32 + o);
    }
    float br[16];
    if (kslot == 0) {
#pragma unroll
        for (int i = 0; i < 16; i++) br[i] = __ldg(b2 + i * 32 + o);
    }
    __syncthreads();
#pragma unroll 1
    for (int n = 0; n < 8; n++) {
        float acc[4] = {0.f, 0.f, 0.f, 0.f};
        float accb = 0.f;
#pragma unroll
        for (int i = 0; i < 16; i++) {
            float v = sx[n * 16 + i];
#pragma unroll
            for (int s = 0; s < 4; s++) acc[s] = fmaf(v, wr[s][i], acc[s]);
            if (kslot == 0) accb = fmaf(v, br[i], accb);
        }
        float* out = g_Y + (n0 + n) * Y1_STRIDE;
#pragma unroll
        for (int s = 0; s < 4; s++) out[(kslot + s * 8) * 32 + o] = acc[s];
        if (kslot == 0) out[1024 + o] = accb;
    }
}

// ---------------------------------------------------------------------------
// K2: conv1 edge kernel. WARP = SOURCE NODE (CSR). Y row loaded ONCE into
// 33 registers; loop over the node's edges: h-MLP + shfl-contract + atomic.
// ---------------------------------------------------------------------------
__global__ __launch_bounds__(256) void edge1(
    const int* __restrict__ ei, const float* __restrict__ ea,
    const float* __restrict__ w1, const float* __restrict__ b1) {
    __shared__ float s_w1[256], s_b1[32];
    int tid = threadIdx.x, lane = tid & 31, warp = tid >> 5;
    s_w1[tid] = w1[tid];
    if (tid < 32) s_b1[tid] = b1[tid];
    __syncthreads();

    int n = blockIdx.x * 8 + warp;
    if (n >= N_NODES) return;
    int cnt = __ldg(g_cnt + n);
    if (cnt == 0) return;
    int start = __ldg(g_off + n) - cnt;

    // Y row into registers (row 32 = bias at offset 32*32 = 1024)
    const float* Yr = g_Y + (long)n * Y1_STRIDE + lane;
    float y[33];
#pragma unroll
    for (int k = 0; k < 33; k++) y[k] = __ldg(Yr + k * 32);

    for (int j = 0; j < cnt; j++) {
        int e = __ldg(g_perm + start + j);
        int dst = __ldg(ei + N_EDGES + e);
        const float4* ear = (const float4*)(ea + (long)e * 8);
        float4 a0 = __ldg(ear), a1 = __ldg(ear + 1);
        float h = s_b1[lane];
        h = fmaf(a0.x, s_w1[0 * 32 + lane], h);
        h = fmaf(a0.y, s_w1[1 * 32 + lane], h);
        h = fmaf(a0.z, s_w1[2 * 32 + lane], h);
        h = fmaf(a0.w, s_w1[3 * 32 + lane], h);
        h = fmaf(a1.x, s_w1[4 * 32 + lane], h);
        h = fmaf(a1.y, s_w1[5 * 32 + lane], h);
        h = fmaf(a1.z, s_w1[6 * 32 + lane], h);
        h = fmaf(a1.w, s_w1[7 * 32 + lane], h);
        h = fmaxf(h, 0.f);

        float msg = y[32];
#pragma unroll
        for (int k = 0; k < 32; k++)
            msg = fmaf(__shfl_sync(0xffffffffu, h, k), y[k], msg);
        atomicAdd(&g_buf1[(long)dst * 32 + lane], msg);
    }
}

// ---------------------------------------------------------------------------
// K4: agg2[n,o] = c2_bias[o] + sum_i relu(agg1[n,i]) * c2_root[i,o]
// ---------------------------------------------------------------------------
__global__ void node_init2(const float* __restrict__ root,
                           const float* __restrict__ bias) {
    int t = blockIdx.x * blockDim.x + threadIdx.x;
    if (t >= N_NODES * 16) return;
    int n = t >> 4, o = t & 15;
    const float* xr = g_buf1 + n * 32;
    float acc = bias[o];
#pragma unroll
    for (int i = 0; i < 32; i++) acc = fmaf(fmaxf(xr[i], 0.f), root[i * 16 + o], acc);
    g_buf2[t] = acc;
}

// ---------------------------------------------------------------------------
// Y2: Y[n,k,o] = sum_i relu(h1[n,i]) * w2[k, i*16+o]  (k<32; row 32 = b2)
// ---------------------------------------------------------------------------
__global__ void y2_kernel(const float* __restrict__ w2,
                          const float* __restrict__ b2) {
    __shared__ float sx[8 * 32];
    int tid = threadIdx.x;
    int o = tid & 15, kb = tid >> 4;
    long n0 = (long)blockIdx.x * 8;
    sx[tid] = fmaxf(g_buf1[n0 * 32 + tid], 0.f);
    float wr[2][32];
#pragma unroll
    for (int s = 0; s < 2; s++) {
        int k = kb + s * 16;
#pragma unroll
        for (int i = 0; i < 32; i++) wr[s][i] = __ldg(w2 + k * 512 + i * 16 + o);
    }
    float br[32];
    if (kb == 0) {
#pragma unroll
        for (int i = 0; i < 32; i++) br[i] = __ldg(b2 + i * 16 + o);
    }
    __syncthreads();
#pragma unroll 1
    for (int n = 0; n < 8; n++) {
        float acc0 = 0.f, acc1 = 0.f, accb = 0.f;
#pragma unroll
        for (int i = 0; i < 32; i++) {
            float v = sx[n * 32 + i];
            acc0 = fmaf(v, wr[0][i], acc0);
            acc1 = fmaf(v, wr[1][i], acc1);
            if (kb == 0) accb = fmaf(v, br[i], accb);
        }
        float* out = g_Y + (n0 + n) * Y2_STRIDE;
        out[kb * 16 + o] = acc0;
        out[(kb + 16) * 16 + o] = acc1;
        if (kb == 0) out[512 + o] = accb;
    }
}

// ---------------------------------------------------------------------------
// K5: conv2 edge kernel. WARP = SOURCE NODE; each half-warp holds the full
// Y2 row (16 cols); processes 2 edges per iteration (sub = half-warp).
// ---------------------------------------------------------------------------
__global__ __launch_bounds__(256) void edge2(
    const int* __restrict__ ei, const float* __restrict__ ea,
    const float* __restrict__ w1, const float* __restrict__ b1) {
    __shared__ float s_w1[256], s_b1[32];
    int tid = threadIdx.x, lane = tid & 31, warp = tid >> 5;
    s_w1[tid] = w1[tid];
    if (tid < 32) s_b1[tid] = b1[tid];
    __syncthreads();

    int n = blockIdx.x * 8 + warp;
    if (n >= N_NODES) return;
    int cnt = __ldg(g_cnt + n);
    if (cnt == 0) return;
    int start = __ldg(g_off + n) - cnt;
    int sub = lane >> 4, o = lane & 15;

    // Y row (row 32 = bias at offset 32*16 = 512); both half-warps load it
    const float* Yr = g_Y + (long)n * Y2_STRIDE + o;
    float y[33];
#pragma unroll
    for (int k = 0; k < 33; k++) y[k] = __ldg(Yr + k * 16);

    for (int j = 0; j < cnt; j += 2) {
        int eA = __ldg(g_perm + start + j);
        int eB = (j + 1 < cnt) ? __ldg(g_perm + start + j + 1) : -1;

        // h for edge A (full warp, lane = k)
        float hA, hB = 0.f;
        {
            const float4* ear = (const float4*)(ea + (long)eA * 8);
            float4 a0 = __ldg(ear), a1 = __ldg(ear + 1);
            float h = s_b1[lane];
            h = fmaf(a0.x, s_w1[0 * 32 + lane], h);
            h = fmaf(a0.y, s_w1[1 * 32 + lane], h);
            h = fmaf(a0.z, s_w1[2 * 32 + lane], h);
            h = fmaf(a0.w, s_w1[3 * 32 + lane], h);
            h = fmaf(a1.x, s_w1[4 * 32 + lane], h);
            h = fmaf(a1.y, s_w1[5 * 32 + lane], h);
            h = fmaf(a1.z, s_w1[6 * 32 + lane], h);
            h = fmaf(a1.w, s_w1[7 * 32 + lane], h);
            hA = fmaxf(h, 0.f);
        }
        if (eB >= 0) {
            const float4* ear = (const float4*)(ea + (long)eB * 8);
            float4 a0 = __ldg(ear), a1 = __ldg(ear + 1);
            float h = s_b1[lane];
            h = fmaf(a0.x, s_w1[0 * 32 + lane], h);
            h = fmaf(a0.y, s_w1[1 * 32 + lane], h);
            h = fmaf(a0.z, s_w1[2 * 32 + lane], h);
            h = fmaf(a0.w, s_w1[3 * 32 + lane], h);
            h = fmaf(a1.x, s_w1[4 * 32 + lane], h);
            h = fmaf(a1.y, s_w1[5 * 32 + lane], h);
            h = fmaf(a1.z, s_w1[6 * 32 + lane], h);
            h = fmaf(a1.w, s_w1[7 * 32 + lane], h);
            hB = fmaxf(h, 0.f);
        }

        int eM = sub ? eB : eA;
        float msg = y[32];
#pragma unroll
        for (int k = 0; k < 32; k++) {
            float ha = __shfl_sync(0xffffffffu, hA, k);
            float hb = __shfl_sync(0xffffffffu, hB, k);
            msg = fmaf(sub ? hb : ha, y[k], msg);
        }
        if (eM >= 0) {
            int dst = __ldg(ei + N_EDGES + eM);
            atomicAdd(&g_buf2[(long)dst * 16 + o], msg);
        }
    }
}

// ---------------------------------------------------------------------------
// K6: relu(agg2) + global_add_pool via per-block shared accumulation
// ---------------------------------------------------------------------------
__global__ void pool_kernel(const int* __restrict__ batch) {
    __shared__ float sg[N_GRAPHS * 16];
    int tid = threadIdx.x;
    for (int i = tid; i < N_GRAPHS * 16; i += blockDim.x) sg[i] = 0.f;
    __syncthreads();
    int t = blockIdx.x * blockDim.x + tid;
    int stride = gridDim.x * blockDim.x;
    for (int n = t; n < N_NODES; n += stride) {
        int b = batch[n];
        const float* r = g_buf2 + n * 16;
#pragma unroll
        for (int f = 0; f < 16; f++)
            atomicAdd(&sg[b * 16 + f], fmaxf(r[f], 0.f));
    }
    __syncthreads();
    for (int i = tid; i < N_GRAPHS * 16; i += blockDim.x)
        if (sg[i] != 0.f) atomicAdd(&g_pool[i], sg[i]);
}

// ---------------------------------------------------------------------------
// K7: head — per-graph MLP
// ---------------------------------------------------------------------------
__global__ void head_kernel(const float* __restrict__ fc1_w,
                            const float* __restrict__ fc1_b,
                            const float* __restrict__ out_w,
                            const float* __restrict__ out_b,
                            float* __restrict__ out) {
    int t = threadIdx.x;
    if (t >= N_GRAPHS) return;
    const float* gr = g_pool + t * 16;
    float r = out_b[0];
#pragma unroll
    for (int o = 0; o < 32; o++) {
        float acc = fc1_b[o];
#pragma unroll
        for (int i = 0; i < 16; i++) acc = fmaf(gr[i], fc1_w[i * 32 + o], acc);
        r = fmaf(fmaxf(acc, 0.f), out_w[o], r);
    }
    out[t] = r;
}

// ---------------------------------------------------------------------------
extern "C" void kernel_launch(void* const* d_in, const int* in_sizes, int n_in,
                              void* d_out, int out_size) {
    const float* x        = (const float*)d_in[0];
    const int*   ei       = (const int*)  d_in[1];
    const float* ea       = (const float*)d_in[2];
    const int*   batch    = (const int*)  d_in[3];
    const float* c1_w1    = (const float*)d_in[4];
    const float* c1_b1    = (const float*)d_in[5];
    const float* c1_w2    = (const float*)d_in[6];
    const float* c1_b2    = (const float*)d_in[7];
    const float* c1_root  = (const float*)d_in[8];
    const float* c1_bias  = (const float*)d_in[9];
    const float* c2_w1    = (const float*)d_in[10];
    const float* c2_b1    = (const float*)d_in[11];
    const float* c2_w2    = (const float*)d_in[12];
    const float* c2_b2    = (const float*)d_in[13];
    const float* c2_root  = (const float*)d_in[14];
    const float* c2_bias  = (const float*)d_in[15];
    const float* fc1_w    = (const float*)d_in[16];
    const float* fc1_b    = (const float*)d_in[17];
    const float* out_w    = (const float*)d_in[18];
    const float* out_b    = (const float*)d_in[19];
    float* out = (float*)d_out;

    // CSR build (perm + counts reused by both convs)
    zero_misc<<<(N_NODES + 255) / 256, 256>>>();
    hist_kernel<<<(N_EDGES + 255) / 256, 256>>>(ei);
    scan_kernel<<<1, 1024>>>();
    scatter_kernel<<<(N_EDGES + 255) / 256, 256>>>(ei);

    // conv1
    node_init1<<<(N_NODES * 32 + 255) / 256, 256>>>(x, c1_root, c1_bias);
    y1_kernel<<<N_NODES / 8, 256>>>(x, c1_w2, c1_b2);
    edge1<<<(N_NODES + 7) / 8, 256>>>(ei, ea, c1_w1, c1_b1);
    // conv2 (relu fused into consumers of g_buf1)
    node_init2<<<(N_NODES * 16 + 255) / 256, 256>>>(c2_root, c2_bias);
    y2_kernel<<<N_NODES / 8, 256>>>(c2_w2, c2_b2);
    edge2<<<(N_NODES + 7) / 8, 256>>>(ei, ea, c2_w1, c2_b1);
    // pool + head
    pool_kernel<<<120, 256>>>(batch);
    head_kernel<<<1, 64>>>(fc1_w, fc1_b, out_w, out_b, out);
}